// round 5
// baseline (speedup 1.0000x reference)
#include <cuda_runtime.h>
#include <cuda_bf16.h>

// Soft-DTW (gamma=0.1), N=M=4096, squared-Euclidean cost, out = |R[N-1,M-1]|.
//
// SINGLE-BLOCK version: 1 block x 1024 threads, 4 sequential row-stripes.
// Thread t of stripe r owns row i = 1024r + t; at stripe-local step s it
// computes cell (i, j = s - t).  u = R[i-1, j] handoffs, ALL intra-block:
//   - lanes 1..31:       shfl.up of neighbor's previous-step q
//   - lane 0, warp 1..31: wslot[2][32] parity double-buffered smem
//   - lane 0, warp 0, stripe r>0: bndsh[j] smem boundary row written by
//     thread 1023 during stripe r-1.  Single buffer is race-free: column j
//     is read at step j and overwritten (for the next stripe) at step
//     j+1023 > j; the per-step __syncthreads orders steps.
// No global scratch, no sentinels, no spins, no reset kernel.
//
// All values kept scaled q = R/(gamma*ln2) so softmin is
//   q = d*KS + m - lg2(2^(m-u) + 2^(m-l) + 2^(m-g)),  m = min(u,l,g)
// via ex2/lg2.approx.ftz; arguments clamped to >= -150 (ftz-identical).

#define NN 4096
#define TPB 1024
#define NSTR (NN / TPB)          // 4 stripes
#define SSTEPS (NN + TPB - 1)    // 5119 steps per stripe

__device__ __forceinline__ float ex2f_(float a) {
    float r; asm("ex2.approx.ftz.f32 %0, %1;" : "=f"(r) : "f"(a)); return r;
}
__device__ __forceinline__ float lg2f_(float a) {
    float r; asm("lg2.approx.ftz.f32 %0, %1;" : "=f"(r) : "f"(a)); return r;
}

__global__ __launch_bounds__(TPB, 1)
void sdtw_single(const float* __restrict__ x, const float* __restrict__ y,
                 float* __restrict__ out) {
    __shared__ float ysh[NN];            // targets, staged once (16 KB)
    __shared__ float bndsh[NN];          // boundary row between stripes (16 KB)
    __shared__ float wslot[2][TPB / 32]; // [step parity][warp] handoff

    const float KS   = 14.426950408889634f;    // 1/(gamma*ln2), gamma=0.1
    const float IKS  = 0.069314718055994531f;  // gamma*ln2
    const float BIGQ = 1.0e8f;                 // "infinity" in q units

    const int tid  = threadIdx.x;
    const int w    = tid >> 5;
    const int lane = tid & 31;

    for (int i = tid; i < NN; i += TPB) ysh[i] = y[i];
    __syncthreads();

    for (int r = 0; r < NSTR; ++r) {
        const int row = r * TPB + tid;
        const float xi = x[row];
        float q = 0.0f;      // my q at previous column (serves as 'left')
        float uprev = 0.0f;  // u used at previous column (serves as 'diag')

        for (int s = 0; s < SSTEPS; ++s) {
            // --- gather u = R[i-1, j] (neighbor's previous-step value) ---
            float u = __shfl_up_sync(0xFFFFFFFFu, q, 1);
            if (lane == 0) {
                if (w > 0)      u = wslot[(s + 1) & 1][w - 1]; // written at s-1
                else if (r > 0) u = (s < NN) ? bndsh[s] : 0.0f; // prev stripe
                else            u = BIGQ;                       // row 0
            }

            // --- compute cell (row, j) ---
            const int j = s - tid;
            if (j >= 0 && j < NN) {
                float l  = (j == 0) ? BIGQ : q;
                float g  = (j == 0) ? ((row == 0) ? 0.0f : BIGQ) : uprev;
                float uu = (row == 0) ? BIGQ : u;
                float dy = xi - ysh[j];
                float dk = dy * dy * KS;
                float m  = fminf(uu, fminf(l, g));
                float e  = ex2f_(fmaxf(m - uu, -150.0f))
                         + ex2f_(fmaxf(m - l,  -150.0f))
                         + ex2f_(fmaxf(m - g,  -150.0f));
                q     = dk + (m - lg2f_(e));
                uprev = uu;
            }

            // --- publish handoffs ---
            if (lane == 31) wslot[s & 1][w] = q;
            if (tid == TPB - 1) {
                const int jj = s - (TPB - 1);
                if (jj >= 0) bndsh[jj] = q;   // boundary row for next stripe
            }
            __syncthreads();
        }

        if (r == NSTR - 1 && tid == TPB - 1)
            out[0] = fabsf(q * IKS);
    }
}

extern "C" void kernel_launch(void* const* d_in, const int* in_sizes, int n_in,
                              void* d_out, int out_size) {
    const float* xin = (const float*)d_in[0];   // inputs  -> rows
    const float* yin = (const float*)d_in[1];   // targets -> cols
    float* outp = (float*)d_out;
    sdtw_single<<<1, TPB>>>(xin, yin, outp);
}

// round 6
// speedup vs baseline: 1.1060x; 1.1060x over previous
#include <cuda_runtime.h>
#include <cuda_bf16.h>

// Soft-DTW (gamma=0.1), N=M=4096, squared-Euclidean cost, out = |R[N-1,M-1]|.
//
// 32 blocks x 128 threads, thread-per-row anti-diagonal wavefront.
// Thread (b,t) owns row i = 128b + t; at block-local step s computes (i, s-t).
//   u = R[i-1,j]:
//     - lanes 1..31:        shfl.up of neighbor's previous-step q
//     - lane 0, warps 1..3: wslot[2][4] parity double-buffered smem (+bar/step)
//     - lane 0, warp 0 (b>0): boundary row streamed from block b-1 through
//       global memory, gated by a RELEASE/ACQUIRE PROGRESS COUNTER:
//         writer:  st.global.cg(value); st.release.gpu(g_prog[b], j+1)
//         reader:  ld.acquire.gpu(g_prog[b-1]) >= c+1  =>  ld.global.cg(value)
//       Stale data from prior graph replays is structurally unreadable
//       (counters reset to 0 per launch; no value sentinels anywhere).
//       A 16-deep register FIFO (x16 unrolled loop, static indices) loads each
//       half-group 8 steps ahead; an early-issued acquire poll keeps the
//       steady state stall-free.
//   All values scaled q = R/(gamma*ln2): softmin via ex2/lg2.approx.ftz with
//   arguments clamped >= -150 (ftz-identical). Proven in R5 at rel_err 4e-5.

#define NN 4096
#define TPB 128
#define NBLK (NN / TPB)          // 32
#define NSTEPS 4224              // >= NN + TPB - 1 = 4223, multiple of 16

// Boundary rows between consecutive blocks + progress counters.
__device__ float g_bnd[(NBLK - 1) * NN];
__device__ int   g_prog[NBLK];

__device__ __forceinline__ float ex2f_(float a) {
    float r; asm("ex2.approx.ftz.f32 %0, %1;" : "=f"(r) : "f"(a)); return r;
}
__device__ __forceinline__ float lg2f_(float a) {
    float r; asm("lg2.approx.ftz.f32 %0, %1;" : "=f"(r) : "f"(a)); return r;
}
__device__ __forceinline__ float ldcgf_(const float* p) {
    float r; asm volatile("ld.global.cg.f32 %0, [%1];" : "=f"(r) : "l"(p)); return r;
}
__device__ __forceinline__ int ldacq_(const int* p) {
    int r; asm volatile("ld.acquire.gpu.global.s32 %0, [%1];" : "=r"(r) : "l"(p)); return r;
}
__device__ __forceinline__ void strel_(int* p, int v) {
    asm volatile("st.release.gpu.global.s32 [%0], %1;" :: "l"(p), "r"(v) : "memory");
}
__device__ __forceinline__ void stcgf_(float* p, float v) {
    asm volatile("st.global.cg.f32 [%0], %1;" :: "l"(p), "f"(v) : "memory");
}

__global__ void sdtw_reset() {
    if (threadIdx.x < NBLK) g_prog[threadIdx.x] = 0;
}

__global__ __launch_bounds__(TPB, 1)
void sdtw_main(const float* __restrict__ x, const float* __restrict__ y,
               float* __restrict__ out) {
    __shared__ float ysh[NN];            // targets, staged once (16 KB)
    __shared__ float wslot[2][TPB / 32]; // [step parity][warp] handoff

    const float KS   = 14.426950408889634f;    // 1/(gamma*ln2), gamma=0.1
    const float IKS  = 0.069314718055994531f;  // gamma*ln2
    const float BIGQ = 1.0e8f;                 // "infinity" in q units

    const int tid  = threadIdx.x;
    const int b    = blockIdx.x;
    const int w    = tid >> 5;
    const int lane = tid & 31;
    const int row  = b * TPB + tid;

    for (int i = tid; i < NN; i += TPB) ysh[i] = y[i];
    const float xi = x[row];

    const float* bnd_in   = g_bnd + (b > 0 ? (b - 1) * NN : 0);
    float*       bnd_out  = g_bnd + (b < NBLK - 1 ? b * NN : 0);
    const int*   prog_in  = &g_prog[b > 0 ? b - 1 : 0];
    int*         prog_out = &g_prog[b < NBLK - 1 ? b : NBLK - 1];
    const bool feeder = (tid == 0) && (b > 0);
    const bool writer = (tid == TPB - 1) && (b < NBLK - 1);

    // Feeder register FIFO: pf[k] holds boundary column for step sb+k.
    float pf[16];
    #pragma unroll
    for (int k = 0; k < 16; ++k) pf[k] = 0.0f;
    int avail = 0, early = 0;
    if (feeder) {
        while ((avail = ldacq_(prog_in)) < 8) {}
        #pragma unroll
        for (int k = 0; k < 8; ++k) pf[k] = ldcgf_(bnd_in + k);
        early = avail;
    }
    __syncthreads();

    float q = 0.0f;      // my q at previous column ('left')
    float uprev = 0.0f;  // u used at previous column ('diag')

#define STEP(S, PFK)                                                          \
    {                                                                         \
        float u = __shfl_up_sync(0xFFFFFFFFu, q, 1);                          \
        if (lane == 0) {                                                      \
            if (w > 0)          u = wslot[((S) + 1) & 1][w - 1];              \
            else if (b == 0)    u = BIGQ;                                     \
            else if ((S) < NN)  u = (PFK);                                    \
        }                                                                     \
        const int j = (S) - tid;                                              \
        if (j >= 0 && j < NN) {                                               \
            float l  = (j == 0) ? BIGQ : q;                                   \
            float g  = (j == 0) ? ((row == 0) ? 0.0f : BIGQ) : uprev;         \
            float uu = (row == 0) ? BIGQ : u;                                 \
            float dy = xi - ysh[j];                                           \
            float dk = dy * dy * KS;                                          \
            float m  = fminf(uu, fminf(l, g));                                \
            float e  = ex2f_(fmaxf(m - uu, -150.0f))                          \
                     + ex2f_(fmaxf(m - l,  -150.0f))                          \
                     + ex2f_(fmaxf(m - g,  -150.0f));                         \
            q     = dk + (m - lg2f_(e));                                      \
            uprev = uu;                                                       \
        }                                                                     \
        if (lane == 31) wslot[(S) & 1][w] = q;                                \
        if (writer) {                                                         \
            const int jj = (S) - (TPB - 1);                                   \
            if (jj >= 0 && jj < NN) {                                         \
                stcgf_(bnd_out + jj, q);                                      \
                strel_(prog_out, jj + 1);                                     \
            }                                                                 \
        }                                                                     \
        __syncthreads();                                                      \
    }

    #pragma unroll 1
    for (int sb = 0; sb < NSTEPS; sb += 16) {
        if (feeder) {
            int lim = sb + 16; if (lim > NN) lim = NN;
            if (avail < lim) {
                if (early > avail) avail = early;
                while (avail < lim) avail = ldacq_(prog_in);
            }
            #pragma unroll
            for (int k = 8; k < 16; ++k) {
                const int c = sb + k;
                if (c < NN) pf[k] = ldcgf_(bnd_in + c);
            }
            early = ldacq_(prog_in);   // early poll for next half-group
        }
        #pragma unroll
        for (int k = 0; k < 8; ++k) STEP(sb + k, pf[k])

        if (feeder) {
            int lim = sb + 24; if (lim > NN) lim = NN;
            if (avail < lim) {
                if (early > avail) avail = early;
                while (avail < lim) avail = ldacq_(prog_in);
            }
            #pragma unroll
            for (int k = 0; k < 8; ++k) {
                const int c = sb + 16 + k;
                if (c < NN) pf[k] = ldcgf_(bnd_in + c);
            }
            early = ldacq_(prog_in);
        }
        #pragma unroll
        for (int k = 8; k < 16; ++k) STEP(sb + k, pf[k])
    }
#undef STEP

    if (tid == TPB - 1 && b == NBLK - 1)
        out[0] = fabsf(q * IKS);
}

extern "C" void kernel_launch(void* const* d_in, const int* in_sizes, int n_in,
                              void* d_out, int out_size) {
    const float* xin = (const float*)d_in[0];   // inputs  -> rows
    const float* yin = (const float*)d_in[1];   // targets -> cols
    float* outp = (float*)d_out;
    sdtw_reset<<<1, 32>>>();
    sdtw_main<<<NBLK, TPB>>>(xin, yin, outp);
}

// round 8
// speedup vs baseline: 3.3042x; 2.9875x over previous
#include <cuda_runtime.h>
#include <cuda_bf16.h>

// Soft-DTW (gamma=0.1), N=M=4096, squared-Euclidean cost, out = |R[N-1,M-1]|.
//
// 32 blocks x 128 threads, thread-per-row anti-diagonal wavefront.
// Thread (b,t) owns row i = 128b + t; at block-local step s computes (i, s-t).
//   u = R[i-1,j]:
//     - lanes 1..31:        shfl.up of neighbor's previous-step q
//     - lane 0, warps 1..3: wslot[2][4] parity double-buffered smem (+bar/step)
//     - lane 0, warp 0 (b>0): boundary row streamed from block b-1 through
//       global memory, gated by a release/acquire progress counter.
//   The writer buffers 8 columns in registers and flushes ONCE per 8-step
//   half-group: 8x st.global.cg + 1x st.release.gpu issued between
//   half-groups, off the per-step barrier path (the R6 per-step release
//   drain cost ~800 cyc/step).
//   R8 fix vs R7: second half-group consumes pf[k] (columns sb+8..sb+15),
//   not pf[k-8] — the k-8 applies only to the wbuf slot index. R7's slip
//   fed boundary values shifted +8 columns (rel_err 4e-3).
//   All values scaled q = R/(gamma*ln2): softmin via ex2/lg2.approx.ftz with
//   arguments clamped >= -150 (ftz-identical). Proven at rel_err 4e-5.

#define NN 4096
#define TPB 128
#define NBLK (NN / TPB)          // 32
#define NSTEPS 4224              // >= NN + TPB - 1 = 4223, multiple of 16

// Boundary rows between consecutive blocks + progress counters.
__device__ float g_bnd[(NBLK - 1) * NN];
__device__ int   g_prog[NBLK];

__device__ __forceinline__ float ex2f_(float a) {
    float r; asm("ex2.approx.ftz.f32 %0, %1;" : "=f"(r) : "f"(a)); return r;
}
__device__ __forceinline__ float lg2f_(float a) {
    float r; asm("lg2.approx.ftz.f32 %0, %1;" : "=f"(r) : "f"(a)); return r;
}
__device__ __forceinline__ float ldcgf_(const float* p) {
    float r; asm volatile("ld.global.cg.f32 %0, [%1];" : "=f"(r) : "l"(p)); return r;
}
__device__ __forceinline__ int ldacq_(const int* p) {
    int r; asm volatile("ld.acquire.gpu.global.s32 %0, [%1];" : "=r"(r) : "l"(p)); return r;
}
__device__ __forceinline__ void strel_(int* p, int v) {
    asm volatile("st.release.gpu.global.s32 [%0], %1;" :: "l"(p), "r"(v) : "memory");
}
__device__ __forceinline__ void stcgf_(float* p, float v) {
    asm volatile("st.global.cg.f32 [%0], %1;" :: "l"(p), "f"(v) : "memory");
}

__global__ void sdtw_reset() {
    if (threadIdx.x < NBLK) g_prog[threadIdx.x] = 0;
}

__global__ __launch_bounds__(TPB, 1)
void sdtw_main(const float* __restrict__ x, const float* __restrict__ y,
               float* __restrict__ out) {
    __shared__ float ysh[NN];            // targets, staged once (16 KB)
    __shared__ float wslot[2][TPB / 32]; // [step parity][warp] handoff

    const float KS   = 14.426950408889634f;    // 1/(gamma*ln2), gamma=0.1
    const float IKS  = 0.069314718055994531f;  // gamma*ln2
    const float BIGQ = 1.0e8f;                 // "infinity" in q units

    const int tid  = threadIdx.x;
    const int b    = blockIdx.x;
    const int w    = tid >> 5;
    const int lane = tid & 31;
    const int row  = b * TPB + tid;

    for (int i = tid; i < NN; i += TPB) ysh[i] = y[i];
    const float xi = x[row];

    const float* bnd_in   = g_bnd + (b > 0 ? (b - 1) * NN : 0);
    float*       bnd_out  = g_bnd + (b < NBLK - 1 ? b * NN : 0);
    const int*   prog_in  = &g_prog[b > 0 ? b - 1 : 0];
    int*         prog_out = &g_prog[b < NBLK - 1 ? b : NBLK - 1];
    const bool feeder = (tid == 0) && (b > 0);
    const bool writer = (tid == TPB - 1) && (b < NBLK - 1);

    // Feeder register FIFO: pf[k] holds boundary column for step sb+k.
    float pf[16];
    #pragma unroll
    for (int k = 0; k < 16; ++k) pf[k] = 0.0f;
    int avail = 0, early = 0;
    if (feeder) {
        while ((avail = ldacq_(prog_in)) < 8) {}
        #pragma unroll
        for (int k = 0; k < 8; ++k) pf[k] = ldcgf_(bnd_in + k);
        early = avail;
    }

    // Writer register buffer: 8 boundary values per half-group.
    float wbuf[8];
    #pragma unroll
    for (int k = 0; k < 8; ++k) wbuf[k] = 0.0f;

    __syncthreads();

    float q = 0.0f;      // my q at previous column ('left')
    float uprev = 0.0f;  // u used at previous column ('diag')

#define STEP(S, PFK, K)                                                       \
    {                                                                         \
        float u = __shfl_up_sync(0xFFFFFFFFu, q, 1);                          \
        if (lane == 0) {                                                      \
            if (w > 0)          u = wslot[((S) + 1) & 1][w - 1];              \
            else if (b == 0)    u = BIGQ;                                     \
            else if ((S) < NN)  u = (PFK);                                    \
        }                                                                     \
        const int j = (S) - tid;                                              \
        if (j >= 0 && j < NN) {                                               \
            float l  = (j == 0) ? BIGQ : q;                                   \
            float g  = (j == 0) ? ((row == 0) ? 0.0f : BIGQ) : uprev;         \
            float uu = (row == 0) ? BIGQ : u;                                 \
            float dy = xi - ysh[j];                                           \
            float dk = dy * dy * KS;                                          \
            float m  = fminf(uu, fminf(l, g));                                \
            float e  = ex2f_(fmaxf(m - uu, -150.0f))                          \
                     + ex2f_(fmaxf(m - l,  -150.0f))                          \
                     + ex2f_(fmaxf(m - g,  -150.0f));                         \
            q     = dk + (m - lg2f_(e));                                      \
            uprev = uu;                                                       \
        }                                                                     \
        if (lane == 31) wslot[(S) & 1][w] = q;                                \
        wbuf[K] = q;                                                          \
        __syncthreads();                                                      \
    }

    // Writer flush: 8 plain .cg stores + ONE release, between half-groups.
#define WFLUSH(SB)                                                            \
    if (writer) {                                                             \
        const int base = (SB) - (TPB - 1);                                    \
        _Pragma("unroll")                                                     \
        for (int k = 0; k < 8; ++k) {                                         \
            const int jj = base + k;                                          \
            if (jj >= 0 && jj < NN) stcgf_(bnd_out + jj, wbuf[k]);            \
        }                                                                     \
        int c = base + 8; if (c > NN) c = NN;                                 \
        if (c > 0) strel_(prog_out, c);                                       \
    }

    #pragma unroll 1
    for (int sb = 0; sb < NSTEPS; sb += 16) {
        if (feeder) {
            int lim = sb + 16; if (lim > NN) lim = NN;
            if (avail < lim) {
                if (early > avail) avail = early;
                while (avail < lim) avail = ldacq_(prog_in);
            }
            #pragma unroll
            for (int k = 8; k < 16; ++k) {
                const int c = sb + k;
                if (c < NN) pf[k] = ldcgf_(bnd_in + c);
            }
            early = ldacq_(prog_in);   // early poll for next half-group
        }
        #pragma unroll
        for (int k = 0; k < 8; ++k) STEP(sb + k, pf[k], k)
        WFLUSH(sb)

        if (feeder) {
            int lim = sb + 24; if (lim > NN) lim = NN;
            if (avail < lim) {
                if (early > avail) avail = early;
                while (avail < lim) avail = ldacq_(prog_in);
            }
            #pragma unroll
            for (int k = 0; k < 8; ++k) {
                const int c = sb + 16 + k;
                if (c < NN) pf[k] = ldcgf_(bnd_in + c);
            }
            early = ldacq_(prog_in);
        }
        #pragma unroll
        for (int k = 8; k < 16; ++k) STEP(sb + k, pf[k], k - 8)
        WFLUSH(sb + 8)
    }
#undef STEP
#undef WFLUSH

    if (tid == TPB - 1 && b == NBLK - 1)
        out[0] = fabsf(q * IKS);
}

extern "C" void kernel_launch(void* const* d_in, const int* in_sizes, int n_in,
                              void* d_out, int out_size) {
    const float* xin = (const float*)d_in[0];   // inputs  -> rows
    const float* yin = (const float*)d_in[1];   // targets -> cols
    float* outp = (float*)d_out;
    sdtw_reset<<<1, 32>>>();
    sdtw_main<<<NBLK, TPB>>>(xin, yin, outp);
}